// round 1
// baseline (speedup 1.0000x reference)
#include <cuda_runtime.h>
#include <math_constants.h>

// Problem constants
constexpr int B = 32, S = 4, K = 11, C = 9, H = 128, W = 128;
constexpr int HW = H * W;          // 16384
constexpr int BSK = B * S * K;     // 1408
constexpr int BS = B * S;          // 128

// Scratch: per-(b,s,k) partials (no allocation allowed -> device globals)
__device__ float g_sq[BSK];   // sum (pred - gt_heatmap)^2 over HW
__device__ float g_max[BSK];  // max of pred over HW
__device__ int   g_idx[BSK];  // argmax (first index on ties)

// Kernel 1: one block per (b,s,k). Fused squared-diff reduction + argmax.
__global__ __launch_bounds__(256) void kp_reduce_kernel(
    const float* __restrict__ hm_preds,   // [B,S,K,H,W]
    const float* __restrict__ heatmaps)   // [B,K,H,W]
{
    const int blk = blockIdx.x;           // b*S*K + s*K + k
    const int k = blk % K;
    const int bs = blk / K;               // b*S + s
    const int b = bs / S;

    const float4* __restrict__ p =
        reinterpret_cast<const float4*>(hm_preds + (size_t)blk * HW);
    const float4* __restrict__ g =
        reinterpret_cast<const float4*>(heatmaps + ((size_t)b * K + k) * HW);

    const int tid = threadIdx.x;

    float sq = 0.0f;
    float mx = -CUDART_INF_F;
    int   mi = 0;

    // HW/4 = 4096 float4s, 256 threads -> 16 iterations/thread
    #pragma unroll 4
    for (int i = tid; i < HW / 4; i += 256) {
        float4 pv = p[i];
        float4 gv = g[i];
        float d0 = pv.x - gv.x, d1 = pv.y - gv.y;
        float d2 = pv.z - gv.z, d3 = pv.w - gv.w;
        sq += d0 * d0 + d1 * d1 + d2 * d2 + d3 * d3;
        const int base = i * 4;
        // strict > keeps the lowest index within this thread (indices ascend)
        if (pv.x > mx) { mx = pv.x; mi = base;     }
        if (pv.y > mx) { mx = pv.y; mi = base + 1; }
        if (pv.z > mx) { mx = pv.z; mi = base + 2; }
        if (pv.w > mx) { mx = pv.w; mi = base + 3; }
    }

    // Warp reduction (sum + argmax with first-index tiebreak)
    #pragma unroll
    for (int off = 16; off > 0; off >>= 1) {
        sq += __shfl_down_sync(0xFFFFFFFFu, sq, off);
        float omx = __shfl_down_sync(0xFFFFFFFFu, mx, off);
        int   omi = __shfl_down_sync(0xFFFFFFFFu, mi, off);
        if (omx > mx || (omx == mx && omi < mi)) { mx = omx; mi = omi; }
    }

    __shared__ float s_sq[8];
    __shared__ float s_mx[8];
    __shared__ int   s_mi[8];
    const int wid = tid >> 5, lane = tid & 31;
    if (lane == 0) { s_sq[wid] = sq; s_mx[wid] = mx; s_mi[wid] = mi; }
    __syncthreads();

    if (wid == 0) {
        sq = (lane < 8) ? s_sq[lane] : 0.0f;
        mx = (lane < 8) ? s_mx[lane] : -CUDART_INF_F;
        mi = (lane < 8) ? s_mi[lane] : 0x7FFFFFFF;
        #pragma unroll
        for (int off = 4; off > 0; off >>= 1) {
            sq += __shfl_down_sync(0xFFFFFFFFu, sq, off);
            float omx = __shfl_down_sync(0xFFFFFFFFu, mx, off);
            int   omi = __shfl_down_sync(0xFFFFFFFFu, mi, off);
            if (omx > mx || (omx == mx && omi < mi)) { mx = omx; mi = omi; }
        }
        if (lane == 0) {
            g_sq[blk]  = sq;
            g_max[blk] = mx;
            g_idx[blk] = mi;
        }
    }
}

// Kernel 2: one warp-block per (b,s). Gathers class preds at argmax, computes
// label loss, and reduces over K. Writes out[0:128]=hm_loss, out[128:256]=lb_loss.
__global__ __launch_bounds__(32) void kp_final_kernel(
    const float* __restrict__ lb_preds,   // [B,S,C,H,W]
    const float* __restrict__ labels,     // [B,K,11]
    float* __restrict__ out)              // [2*B*S]
{
    const int bs = blockIdx.x;            // b*S + s
    const int b = bs / S;
    const int t = threadIdx.x;            // 32 threads; t < K active

    float hm = 0.0f, lb = 0.0f;
    if (t < K) {
        const int blk = bs * K + t;
        hm = g_sq[blk];
        const int   idx  = g_idx[blk];
        const float conf = g_max[blk];
        const int x = idx / W;    // m == H == 128 in reference; pos == idx
        const int y = idx % W;

        const float* __restrict__ lab = labels + ((size_t)b * K + t) * 11;
        const float gx = lab[9], gy = lab[10];
        const bool valid = (gx >= 0.0f) && (gy >= 0.0f) &&
                           (gx < (float)H) && (gy < (float)W);

        float cls = 0.0f;
        const float* __restrict__ lp = lb_preds + (size_t)bs * C * HW + idx;
        #pragma unroll
        for (int c = 0; c < C; c++) {
            float d = lp[(size_t)c * HW] - lab[c];
            cls += d * d;
        }
        const float dx = gx - (float)x;
        const float dy = gy - (float)y;
        const float cf = 1.0f - conf;
        lb = valid ? (cls + dx * dx + dy * dy + cf * cf) : 0.0f;
    }

    #pragma unroll
    for (int off = 16; off > 0; off >>= 1) {
        hm += __shfl_down_sync(0xFFFFFFFFu, hm, off);
        lb += __shfl_down_sync(0xFFFFFFFFu, lb, off);
    }
    if (t == 0) {
        out[bs]      = hm;   // hm_loss [B,S]
        out[BS + bs] = lb;   // lb_loss [B,S]
    }
}

extern "C" void kernel_launch(void* const* d_in, const int* in_sizes, int n_in,
                              void* d_out, int out_size) {
    const float* hm_preds = (const float*)d_in[0];  // [B,S,K,H,W]
    const float* lb_preds = (const float*)d_in[1];  // [B,S,C,H,W]
    const float* heatmaps = (const float*)d_in[2];  // [B,K,H,W]
    const float* labels   = (const float*)d_in[3];  // [B,K,11]
    float* out = (float*)d_out;

    kp_reduce_kernel<<<BSK, 256>>>(hm_preds, heatmaps);
    kp_final_kernel<<<BS, 32>>>(lb_preds, labels, out);
}

// round 2
// speedup vs baseline: 1.1664x; 1.1664x over previous
#include <cuda_runtime.h>
#include <math_constants.h>

// Problem constants
constexpr int B = 32, S = 4, K = 11, C = 9, H = 128, W = 128;
constexpr int HW = H * W;          // 16384
constexpr int BSK = B * S * K;     // 1408
constexpr int BS = B * S;          // 128

// Zero-init the output (poisoned by harness; we accumulate with atomics).
__global__ __launch_bounds__(256) void kp_zero_kernel(float* __restrict__ out) {
    out[threadIdx.x] = 0.0f;       // exactly 2*BS = 256 elements
}

// One block per (b,s,k): fused squared-diff reduction + argmax + label-loss
// epilogue (scattered gathers + atomic accumulation into out).
__global__ __launch_bounds__(256) void kp_fused_kernel(
    const float* __restrict__ hm_preds,   // [B,S,K,H,W]
    const float* __restrict__ lb_preds,   // [B,S,C,H,W]
    const float* __restrict__ heatmaps,   // [B,K,H,W]
    const float* __restrict__ labels,     // [B,K,11]
    float* __restrict__ out)              // [2*B*S]: [hm | lb]
{
    const int blk = blockIdx.x;           // b*S*K + s*K + k
    const int k = blk % K;
    const int bs = blk / K;               // b*S + s
    const int b = bs / S;

    const float4* __restrict__ p =
        reinterpret_cast<const float4*>(hm_preds + (size_t)blk * HW);
    const float4* __restrict__ g =
        reinterpret_cast<const float4*>(heatmaps + ((size_t)b * K + k) * HW);

    const int tid = threadIdx.x;

    float sq = 0.0f;
    float mx = -CUDART_INF_F;
    int   mi = 0;

    // HW/4 = 4096 float4s, 256 threads -> 16 iterations/thread
    #pragma unroll 4
    for (int i = tid; i < HW / 4; i += 256) {
        const float4 pv = __ldcs(&p[i]);   // streaming: read once, evict first
        const float4 gv = __ldg(&g[i]);    // re-read x4 across s: keep in L2
        float d0 = pv.x - gv.x, d1 = pv.y - gv.y;
        float d2 = pv.z - gv.z, d3 = pv.w - gv.w;
        sq += d0 * d0 + d1 * d1 + d2 * d2 + d3 * d3;
        const int base = i * 4;
        // strict > keeps the lowest index within this thread (indices ascend)
        if (pv.x > mx) { mx = pv.x; mi = base;     }
        if (pv.y > mx) { mx = pv.y; mi = base + 1; }
        if (pv.z > mx) { mx = pv.z; mi = base + 2; }
        if (pv.w > mx) { mx = pv.w; mi = base + 3; }
    }

    // Warp reduction (sum + argmax with first-index tiebreak)
    #pragma unroll
    for (int off = 16; off > 0; off >>= 1) {
        sq += __shfl_down_sync(0xFFFFFFFFu, sq, off);
        float omx = __shfl_down_sync(0xFFFFFFFFu, mx, off);
        int   omi = __shfl_down_sync(0xFFFFFFFFu, mi, off);
        if (omx > mx || (omx == mx && omi < mi)) { mx = omx; mi = omi; }
    }

    __shared__ float s_sq[8];
    __shared__ float s_mx[8];
    __shared__ int   s_mi[8];
    const int wid = tid >> 5, lane = tid & 31;
    if (lane == 0) { s_sq[wid] = sq; s_mx[wid] = mx; s_mi[wid] = mi; }
    __syncthreads();

    if (wid == 0) {
        sq = (lane < 8) ? s_sq[lane] : 0.0f;
        mx = (lane < 8) ? s_mx[lane] : -CUDART_INF_F;
        mi = (lane < 8) ? s_mi[lane] : 0x7FFFFFFF;
        #pragma unroll
        for (int off = 4; off > 0; off >>= 1) {
            sq += __shfl_down_sync(0xFFFFFFFFu, sq, off);
            float omx = __shfl_down_sync(0xFFFFFFFFu, mx, off);
            int   omi = __shfl_down_sync(0xFFFFFFFFu, mi, off);
            if (omx > mx || (omx == mx && omi < mi)) { mx = omx; mi = omi; }
        }

        // ---- Label-loss epilogue, fused: broadcast result to warp 0 ----
        sq = __shfl_sync(0xFFFFFFFFu, sq, 0);
        mx = __shfl_sync(0xFFFFFFFFu, mx, 0);
        mi = __shfl_sync(0xFFFFFFFFu, mi, 0);

        const float* __restrict__ lab = labels + ((size_t)b * K + k) * 11;

        // lanes 0..8: one class-channel gather each at the argmax position
        float part = 0.0f;
        if (lane < C) {
            const float v = __ldg(&lb_preds[((size_t)bs * C + lane) * HW + mi]);
            const float d = v - __ldg(&lab[lane]);
            part = d * d;
        }
        #pragma unroll
        for (int off = 8; off > 0; off >>= 1)
            part += __shfl_down_sync(0xFFFFFFFFu, part, off);

        if (lane == 0) {
            const float gx = __ldg(&lab[9]);
            const float gy = __ldg(&lab[10]);
            const bool valid = (gx >= 0.0f) && (gy >= 0.0f) &&
                               (gx < (float)H) && (gy < (float)W);
            const int x = mi / W;  // m == H == W == 128: pos == idx
            const int y = mi % W;
            const float dx = gx - (float)x;
            const float dy = gy - (float)y;
            const float cf = 1.0f - mx;
            const float lb = valid ? (part + dx * dx + dy * dy + cf * cf) : 0.0f;

            atomicAdd(&out[bs],      sq);  // hm_loss [B,S]
            atomicAdd(&out[BS + bs], lb);  // lb_loss [B,S]
        }
    }
}

extern "C" void kernel_launch(void* const* d_in, const int* in_sizes, int n_in,
                              void* d_out, int out_size) {
    const float* hm_preds = (const float*)d_in[0];  // [B,S,K,H,W]
    const float* lb_preds = (const float*)d_in[1];  // [B,S,C,H,W]
    const float* heatmaps = (const float*)d_in[2];  // [B,K,H,W]
    const float* labels   = (const float*)d_in[3];  // [B,K,11]
    float* out = (float*)d_out;

    kp_zero_kernel<<<1, 2 * BS>>>(out);
    kp_fused_kernel<<<BSK, 256>>>(hm_preds, lb_preds, heatmaps, labels, out);
}